// round 3
// baseline (speedup 1.0000x reference)
#include <cuda_runtime.h>

// LFQ quantizer, factorized softmax formulation, atomic-free.
// N = 8192 samples, D = 14 dims, K = 16384 codes.
//
// p_j = prod_d sigmoid(400 * x_d * c_jd)   (exact factorization of softmax(s/T))
// sample entropy = sum_d binary_entropy(sigmoid(400 x_d))
// avg_probs[h*128+l] = (1/N) sum_i phi_i[h] * plo_i[l]  -> 128x128 outer-product GEMM
//
// Stage A: 128 blocks compute q_out, per-block commit/sampH partials, and a
//          per-block 128x128 probability outer-product partial -> scratch (STG).
// Stage B: 64 blocks reduce the 128 partials per code + entropy term.
// Stage C: 1 block assembles the 4 scalar outputs.

#define DIMS 14
#define SPB 64            // samples per block in main kernel
#define NCODES 16384
#define NBLK 128          // main-kernel blocks (8192 / SPB)

__device__ float g_part[NBLK * NCODES];   // per-block outer-product partials (8 MB)
__device__ float g_commitP[NBLK];
__device__ float g_sampHP[NBLK];
__device__ float g_entP[64];

__global__ __launch_bounds__(256) void lfq_main_kernel(const float* __restrict__ x,
                                                       float* __restrict__ out) {
    __shared__ float qp[SPB][DIMS];    // P(bit=1) per sample/dim, computed stably
    __shared__ float qm[SPB][DIMS];    // P(bit=0)
    __shared__ float s_plo[8][128];
    __shared__ float s_phi[8][128];
    __shared__ float red[256];

    const int tid = threadIdx.x;
    const int s0 = blockIdx.x * SPB;

    float commit_acc = 0.f;
    float h_acc = 0.f;

    // ---- per-element pass: sign output, commit loss, sample entropy, per-dim probs ----
    for (int e = tid; e < SPB * DIMS; e += 256) {
        int gi = s0 * DIMS + e;
        float xv = x[gi];
        float qz = (xv > 0.f) ? 1.f : -1.f;
        out[gi] = qz;
        float dq = xv - qz;
        commit_acc += dq * dq;

        float z = 400.f * xv;             // 2 * (logits/T coefficient)
        float t = fabsf(z);
        float u = expf(-t);               // <= 1, no overflow
        float inv = 1.f / (1.f + u);
        // stable binary entropy of sigmoid(z): log(1+u) + t*u/(1+u)
        h_acc += log1pf(u) + t * u * inv;

        float qbig = inv;                 // sigmoid(|z|)
        float qsml = u * inv;             // sigmoid(-|z|), no cancellation
        int s = e / DIMS, d = e - s * DIMS;
        if (z >= 0.f) { qp[s][d] = qbig; qm[s][d] = qsml; }
        else          { qp[s][d] = qsml; qm[s][d] = qbig; }
    }

    // ---- block-reduce commit & entropy partials -> per-block slots (no atomics) ----
    red[tid] = commit_acc;
    __syncthreads();
    for (int off = 128; off; off >>= 1) {
        if (tid < off) red[tid] += red[tid + off];
        __syncthreads();
    }
    if (tid == 0) g_commitP[blockIdx.x] = red[0];
    __syncthreads();
    red[tid] = h_acc;
    __syncthreads();
    for (int off = 128; off; off >>= 1) {
        if (tid < off) red[tid] += red[tid + off];
        __syncthreads();
    }
    if (tid == 0) g_sampHP[blockIdx.x] = red[0];

    // ---- outer-product accumulation: M[h][l] += phi_i[h] * plo_i[l] ----
    float acc[8][8];
    #pragma unroll
    for (int r = 0; r < 8; ++r)
        #pragma unroll
        for (int c = 0; c < 8; ++c)
            acc[r][c] = 0.f;

    const int tr = tid >> 4;   // 0..15  (hi rows, strided by 16)
    const int tc = tid & 15;   // 0..15  (lo cols, strided by 16)

    for (int ch = 0; ch < SPB / 8; ++ch) {
        __syncthreads();
        // build plo/phi for 8 samples: 2048 entries, 256 threads, 8 iters
        for (int k2 = tid; k2 < 2048; k2 += 256) {
            int which = k2 >> 10;          // 0 = plo (bits 0..6), 1 = phi (bits 7..13)
            int s = (k2 >> 7) & 7;
            int e = k2 & 127;
            int base = ch * 8 + s;
            const float* qpb = which ? &qp[base][7] : &qp[base][0];
            const float* qmb = which ? &qm[base][7] : &qm[base][0];
            float p = 1.f;
            #pragma unroll
            for (int d = 0; d < 7; ++d)
                p *= ((e >> d) & 1) ? qpb[d] : qmb[d];
            if (which) s_phi[s][e] = p; else s_plo[s][e] = p;
        }
        __syncthreads();
        #pragma unroll
        for (int s = 0; s < 8; ++s) {
            float ph[8], pl[8];
            #pragma unroll
            for (int r = 0; r < 8; ++r) ph[r] = s_phi[s][tr + 16 * r];
            #pragma unroll
            for (int c = 0; c < 8; ++c) pl[c] = s_plo[s][tc + 16 * c];
            #pragma unroll
            for (int r = 0; r < 8; ++r)
                #pragma unroll
                for (int c = 0; c < 8; ++c)
                    acc[r][c] += ph[r] * pl[c];
        }
    }

    // ---- write per-block partial tile (plain coalesced STG, no atomics) ----
    float* pdst = &g_part[blockIdx.x * NCODES];
    #pragma unroll
    for (int r = 0; r < 8; ++r)
        #pragma unroll
        for (int c = 0; c < 8; ++c)
            pdst[(tr + 16 * r) * 128 + (tc + 16 * c)] = acc[r][c];
}

// Stage B: one thread per code; sum 128 block-partials, entropy term, block-reduce.
__global__ __launch_bounds__(256) void lfq_reduce_kernel(float n_samples) {
    __shared__ float red[256];
    const int tid = threadIdx.x;
    const int code = blockIdx.x * 256 + tid;
    const float invN = 1.f / n_samples;

    float s = 0.f;
    #pragma unroll 8
    for (int b = 0; b < NBLK; ++b)
        s += g_part[b * NCODES + code];

    float m = s * invN;
    float acc = -m * logf(m + 1e-5f);

    red[tid] = acc;
    __syncthreads();
    for (int off = 128; off; off >>= 1) {
        if (tid < off) red[tid] += red[tid + off];
        __syncthreads();
    }
    if (tid == 0) g_entP[blockIdx.x] = red[0];
}

// Stage C: assemble the 4 scalar outputs.
__global__ void lfq_final_kernel(float* __restrict__ out, int qn, int out_size, float n_samples) {
    __shared__ float re[128], rc[128], rh[128];
    const int tid = threadIdx.x;

    float e = (tid < 64) ? g_entP[tid] : 0.f;
    float c = g_commitP[tid];
    float h = g_sampHP[tid];
    re[tid] = e; rc[tid] = c; rh[tid] = h;
    __syncthreads();
    for (int off = 64; off; off >>= 1) {
        if (tid < off) { re[tid] += re[tid + off]; rc[tid] += rc[tid + off]; rh[tid] += rh[tid + off]; }
        __syncthreads();
    }
    if (tid == 0 && out_size >= qn + 4) {
        float invN = 1.f / n_samples;
        float avg_e = re[0];
        float samp_e = rh[0] * invN;
        float commit = rc[0] / (n_samples * (float)DIMS);
        out[qn + 0] = samp_e - avg_e;   // entropy_aux_loss (weights 1.0/1.0)
        out[qn + 1] = samp_e;           // sample_entropy
        out[qn + 2] = avg_e;            // avg_entropy
        out[qn + 3] = commit;           // commit_loss
    }
}

extern "C" void kernel_launch(void* const* d_in, const int* in_sizes, int n_in,
                              void* d_out, int out_size) {
    const float* x = (const float*)d_in[0];
    float* out = (float*)d_out;
    int qn = in_sizes[0];              // 8*1024*14 = 114688 elements of q_out
    float n_samples = (float)(qn / DIMS);  // 8192

    lfq_main_kernel<<<NBLK, 256>>>(x, out);
    lfq_reduce_kernel<<<64, 256>>>(n_samples);
    lfq_final_kernel<<<1, 128>>>(out, qn, out_size, n_samples);
}

// round 5
// speedup vs baseline: 2.8442x; 2.8442x over previous
#include <cuda_runtime.h>

// LFQ quantizer — sparse factorized softmax, single fused kernel.
// N = 8192 samples, D = 14 dims, K = 16384 codes, T = 0.01.
//
// softmax factorizes: p_j = prod_d sigmoid(400 x_d c_jd).
// With T=0.01 the per-dim flip ratio u_d = e^{-400|x_d|} is > 1e-8 only for
// |x_d| < 0.046 (~3.7% of dims). Enumerate subsets of the "soft" dims:
//   p(j_main ^ S) = p_main * prod_{d in S} u_d,   p_main = prod_d 1/(1+u_d).
// Expected enumerated codes/sample ~ 1.7 -> ~14K scattered atomics total.
// sample_entropy = sum_d binary_entropy(sigmoid(400 x_d))  (exact, factorized).
//
// Single kernel: phase1 per-sample work + scatter, grid spin-barrier,
// phase2 entropy over avg_probs + scratch re-zero, last-block writes scalars
// and resets counters (graph-replay safe; __device__ globals start zeroed).

#define DIMS 14
#define NCODES 16384
#define BTH 64
#define UTH 1e-8f

__device__ float g_M[NCODES];           // sum of probs per code (zeroed each run)
__device__ float g_commit, g_sampH, g_ent;
__device__ unsigned int g_bar, g_ticket;

__global__ __launch_bounds__(BTH) void lfq_fused(const float* __restrict__ x,
                                                 float* __restrict__ out,
                                                 int qn, int out_size,
                                                 int nblocks, int codes_per_blk,
                                                 float inv_n) {
    __shared__ float u_sm[BTH][DIMS];
    __shared__ float c2[2], h2[2], e2[2];

    const int tid = threadIdx.x;
    const int gid = blockIdx.x * BTH + tid;     // sample id

    // ================= phase 1: per-sample =================
    float commit_acc = 0.f, h_acc = 0.f;
    float p_main = 1.f;
    int j_main = 0;
    unsigned soft = 0;

    const float* xp = x + gid * DIMS;
    float* op = out + gid * DIMS;

    #pragma unroll
    for (int d = 0; d < DIMS; ++d) {
        float xv = xp[d];
        float qz = (xv > 0.f) ? 1.f : -1.f;
        op[d] = qz;
        float dq = xv - qz;
        commit_acc += dq * dq;

        float t = fabsf(400.f * xv);
        float u = expf(-t);                      // flip ratio e^{-|z|}
        if (xv > 0.f) j_main |= (1 << d);

        if (u > 1e-4f) {                         // soft-ish: exact formulas
            float inv = 1.f / (1.f + u);
            h_acc += log1pf(u) + t * u * inv;    // binary entropy, stable
            p_main *= inv;
        } else {                                 // hard: 1st-order, err ~ u^2
            h_acc += u * (1.f + t);
            p_main *= (1.f - u);
        }
        u_sm[tid][d] = u;
        if (u > UTH) soft |= (1u << d);
    }

    // enumerate all subsets of `soft` (incl. empty), scatter to g_M
    unsigned m = 0;
    do {
        float p = p_main;
        unsigned r = m;
        while (r) {
            int d = __ffs(r) - 1;
            p *= u_sm[tid][d];
            r &= r - 1;
        }
        atomicAdd(&g_M[j_main ^ (int)m], p);
        m = (m - soft) & soft;                   // next subset
    } while (m);

    // block-reduce commit & sample-entropy partials (2 warps)
    #pragma unroll
    for (int off = 16; off; off >>= 1) {
        commit_acc += __shfl_down_sync(0xffffffffu, commit_acc, off);
        h_acc      += __shfl_down_sync(0xffffffffu, h_acc, off);
    }
    if ((tid & 31) == 0) { c2[tid >> 5] = commit_acc; h2[tid >> 5] = h_acc; }
    __syncthreads();
    if (tid == 0) {
        atomicAdd(&g_commit, c2[0] + c2[1]);
        atomicAdd(&g_sampH,  h2[0] + h2[1]);
    }

    // ================= grid barrier (all blocks co-resident) =================
    if (tid == 0) {
        __threadfence();
        atomicAdd(&g_bar, 1u);
        while (*(volatile unsigned int*)&g_bar < (unsigned)nblocks)
            __nanosleep(64);
    }
    __syncthreads();
    __threadfence();

    // ================= phase 2: entropy of avg_probs + re-zero =================
    float ea = 0.f;
    const int base = blockIdx.x * codes_per_blk;
    for (int i = tid; i < codes_per_blk; i += BTH) {
        int c = base + i;
        float mm = g_M[c] * inv_n;
        ea -= mm * logf(mm + 1e-5f);             // mm==0 -> contributes 0
        g_M[c] = 0.f;                            // reset for next graph replay
    }
    #pragma unroll
    for (int off = 16; off; off >>= 1)
        ea += __shfl_down_sync(0xffffffffu, ea, off);
    if ((tid & 31) == 0) e2[tid >> 5] = ea;
    __syncthreads();
    if (tid == 0) {
        atomicAdd(&g_ent, e2[0] + e2[1]);
        __threadfence();
        unsigned tk = atomicAdd(&g_ticket, 1u);
        if (tk == (unsigned)nblocks - 1) {       // last block: finalize
            float samp = atomicAdd(&g_sampH, 0.f) * inv_n;
            float avg  = atomicAdd(&g_ent, 0.f);
            float cm   = atomicAdd(&g_commit, 0.f) * inv_n * (1.f / (float)DIMS);
            if (out_size >= qn + 4) {
                out[qn + 0] = samp - avg;        // entropy_aux_loss
                out[qn + 1] = samp;              // sample_entropy
                out[qn + 2] = avg;               // avg_entropy
                out[qn + 3] = cm;                // commit_loss
            }
            g_commit = 0.f; g_sampH = 0.f; g_ent = 0.f;
            g_bar = 0u; g_ticket = 0u;           // reset for next replay
        }
    }
}

extern "C" void kernel_launch(void* const* d_in, const int* in_sizes, int n_in,
                              void* d_out, int out_size) {
    const float* x = (const float*)d_in[0];
    float* out = (float*)d_out;
    int qn = in_sizes[0];                 // 8*1024*14 = 114688
    int nsamp = qn / DIMS;                // 8192
    int nblocks = nsamp / BTH;            // 128 (all co-resident: 148 SMs)
    int codes_per_blk = NCODES / nblocks; // 128
    float inv_n = 1.f / (float)nsamp;

    lfq_fused<<<nblocks, BTH>>>(x, out, qn, out_size, nblocks, codes_per_blk, inv_n);
}